// round 17
// baseline (speedup 1.0000x reference)
#include <cuda_runtime.h>
#include <cuda_fp16.h>
#include <math.h>
#include <stdint.h>

#define NB 256
#define NI 512   // outputs (i)
#define NJ 512   // inputs  (j) -> contraction K
#define NW 64

// Scratch (static device arrays: allocation rules OK)
// j-index stored PERMUTED within each 16-block (permj) -> LDS.64 fragment loads.
__device__ __half g_inT  [(size_t)NW * NB * NJ];   // [w][b][pj]  16.8 MB fp16
__device__ __half g_dropT[(size_t)NW * NI * NJ];   // [w][i][pj]  33.5 MB fp16
__device__ __half g_outTh[(size_t)NW * NB * NI];   // [w][b][i]   16.8 MB fp16

// permute j within its 16-block: pairs stay adjacent, k and k+8 pair up.
// Quad {2q,2q+1,2q+8,2q+9} -> contiguous positions 4q..4q+3 (8B store unit).
__device__ __forceinline__ int permj(int j) {
    return (j & ~15) | (((j >> 1) & 3) << 2) | (((j >> 3) & 1) << 1) | (j & 1);
}

// ---------------------------------------------------------------------------
// Kernel 1 (merged prep): blocks [0,256) = dropT, blocks [256,4352) = tin.
//
// dropT (quad-vectorized): each thread owns a j-quad {2q,2q+1,2q+8,2q+9} of
// one i-row -> 4 ring-constant sets, and per w stores ONE 8B chunk at the
// contiguous permuted positions 4q..4q+3.  Same arithmetic/order as R16
// (rel_err must be bit-identical); 4x fewer stores + index ALU.
// denom2 = 1 - 2 at cos + at^2;  Kerr term (~2.7e-19 rad) below fp32 eps;
// __cosf validated R6/R14.
// ---------------------------------------------------------------------------
__global__ void __launch_bounds__(256) prep_kernel(
        const float* __restrict__ in,
        const float* __restrict__ phase_shift,
        const float* __restrict__ coupling) {
    __shared__ float s[32][65];
    const int t = threadIdx.x;

    if (blockIdx.x < 256) {
        // ---- dropT part: 65536 threads, one j-quad each ----
        const int i    = blockIdx.x * 2 + (t >> 7);    // 0..511
        const int quad = t & 127;                       // 0..127
        const int b16  = quad >> 2;                     // which 16-block of j
        const int q    = quad & 3;
        const int j0   = b16 * 16;

        const int jj[4] = { j0 + 2 * q, j0 + 2 * q + 1, j0 + 2 * q + 8, j0 + 2 * q + 9 };

        float base[4], dphi[4], A2[4], twoAt[4], coef[4];
#pragma unroll
        for (int u = 0; u < 4; u++) {
            const int k = i * NJ + jj[u];
            const double WLMIN = 1.53e-06, WLMAX = 1.57e-06;
            double c    = WLMIN + (WLMAX - WLMIN) * ((double)k / (double)(NI * NJ));
            double pref = (4.0 * M_PI * M_PI * 4.2 * 5e-06) / (c * c);   // 2*pi/fsr
            base[u] = (float)(pref * (WLMIN - c)) + phase_shift[k];
            dphi[u] = (float)(pref * ((WLMAX - WLMIN) / 63.0));

            float kap = fminf(fmaxf(coupling[k], 0.1f), 0.9f);
            float tc  = sqrtf(1.0f - kap * kap);
            const float alpha = (float)(1.0 - M_PI / 15000.0);
            float at  = alpha * tc;
            A2[u]    = 1.0f + at * at;
            twoAt[u] = 2.0f * at;
            coef[u]  = kap * kap * alpha;
        }

        // store base: positions i*NJ + j0 + 4q + {0..3}
        __half* dst = g_dropT + (size_t)i * NJ + j0 + 4 * q;
#pragma unroll 4
        for (int w = 0; w < NW; w++) {
            float d[4];
#pragma unroll
            for (int u = 0; u < 4; u++) {
                float ph = fmaf((float)w, dphi[u], base[u]);
                d[u] = __fdividef(coef[u], A2[u] - twoAt[u] * __cosf(ph));
            }
            __half2 h[2];
            h[0] = __floats2half2_rn(d[0], d[1]);
            h[1] = __floats2half2_rn(d[2], d[3]);
            *(uint2*)&dst[(size_t)w * NI * NJ] = *(uint2*)h;
        }
    } else {
        // ---- tin part (unchanged from R16) ----
        const int blk = blockIdx.x - 256;
        const int b  = blk >> 4;
        const int j0 = (blk & 15) * 32;

        {   // load 32 j-rows x 64 w (256B per row)
            int r = t >> 3, wq = (t & 7) * 8;
            const float4* src = (const float4*)(in + ((size_t)b * NJ + j0 + r) * NW + wq);
            float4 v0 = src[0], v1 = src[1];
            s[r][wq + 0] = v0.x; s[r][wq + 1] = v0.y; s[r][wq + 2] = v0.z; s[r][wq + 3] = v0.w;
            s[r][wq + 4] = v1.x; s[r][wq + 5] = v1.y; s[r][wq + 6] = v1.z; s[r][wq + 7] = v1.w;
        }
        __syncthreads();
        {   // write 64 w-rows x 32 j as fp16, permuted (4B pair stores)
            int w = t >> 2, jg = (t & 3) * 8;
            __half* dst = g_inT + ((size_t)w * NB + b) * NJ + j0;
#pragma unroll
            for (int u = 0; u < 4; u++) {
                __half2 h = __floats2half2_rn(s[jg + 2 * u][w], s[jg + 2 * u + 1][w]);
                *(__half2*)&dst[permj(jg + 2 * u)] = h;
            }
        }
    }
}

// ---------------------------------------------------------------------------
// Kernel 2: mma.sync fp16 m16n8k16 GEMM per w-plane (R16-proven, unchanged).
// 3-stage cp.async ring, one sync per chunk, loads before compute.
// ---------------------------------------------------------------------------
#define TM 128
#define TN 128
#define KC 32                    // halves per chunk
#define NCH (NJ / KC)            // 16
#define RSB 96                   // smem row stride bytes (64B data + 32B pad)
#define SBYT (128 * RSB)         // 12288 bytes per operand-stage
#define SMEM_REQ (6 * SBYT)      // 73728 bytes (3 stages x {A,B})

#define CPA(s, g) asm volatile("cp.async.ca.shared.global [%0], [%1], 16;" :: "r"(s), "l"(g))

#define MMA_F16(c, a0, a1, a2, a3, b0, b1) \
    asm volatile("mma.sync.aligned.m16n8k16.row.col.f32.f16.f16.f32 " \
        "{%0,%1,%2,%3}, {%4,%5,%6,%7}, {%8,%9}, {%0,%1,%2,%3};" \
        : "+f"((c)[0]), "+f"((c)[1]), "+f"((c)[2]), "+f"((c)[3]) \
        : "r"(a0), "r"(a1), "r"(a2), "r"(a3), "r"(b0), "r"(b1))

#define LDSD(r0_, r1_, addr) \
    asm volatile("ld.shared.v2.b32 {%0,%1}, [%2];" : "=r"(r0_), "=r"(r1_) : "r"(addr))

static __device__ __forceinline__ uint32_t smem_u32(const void* p) {
    uint32_t a;
    asm("{ .reg .u64 t; cvta.to.shared.u64 t, %1; cvt.u32.u64 %0, t; }" : "=r"(a) : "l"(p));
    return a;
}

__global__ void __launch_bounds__(256, 2) gemm_kernel() {
    extern __shared__ char smem[];           // [A0|A1|A2|B0|B1|B2], 12288B each
    const uint32_t sbase = smem_u32(smem);

    const int tid = threadIdx.x;
    const int w   = blockIdx.x;
    const int b0  = blockIdx.y * TM;
    const int i0  = blockIdx.z * TN;

    const int r0 = tid >> 2, wc = tid & 3;
    const int r1 = r0 + 64;
    const __half* gA = g_inT   + ((size_t)w * NB + b0) * NJ;
    const __half* gB = g_dropT + ((size_t)w * NI + i0) * NJ;
    const uint32_t soA0 = (uint32_t)(r0 * RSB + wc * 16);
    const uint32_t soA1 = (uint32_t)(r1 * RSB + wc * 16);

#define STAGE(slot, jc) do { \
    CPA(sbase + (slot) * SBYT + soA0,       (const char*)(gA + (size_t)r0 * NJ + (jc)) + wc * 16); \
    CPA(sbase + (slot) * SBYT + soA1,       (const char*)(gA + (size_t)r1 * NJ + (jc)) + wc * 16); \
    CPA(sbase + (3 + (slot)) * SBYT + soA0, (const char*)(gB + (size_t)r0 * NJ + (jc)) + wc * 16); \
    CPA(sbase + (3 + (slot)) * SBYT + soA1, (const char*)(gB + (size_t)r1 * NJ + (jc)) + wc * 16); \
    asm volatile("cp.async.commit_group;" ::: "memory"); \
} while (0)

    STAGE(0, 0);
    STAGE(1, KC);

    const int lane = tid & 31, wid = tid >> 5;
    const int g = lane >> 2, q = lane & 3;
    const int wm = (wid >> 2) * 64;
    const int wn = (wid & 3) * 32;

    float acc[4][4][4];
#pragma unroll
    for (int mt = 0; mt < 4; mt++)
#pragma unroll
        for (int nt = 0; nt < 4; nt++)
#pragma unroll
            for (int r = 0; r < 4; r++) acc[mt][nt][r] = 0.0f;

    for (int ch = 0; ch < NCH; ch++) {
        if (ch < NCH - 1) asm volatile("cp.async.wait_group 1;" ::: "memory");
        else              asm volatile("cp.async.wait_group 0;" ::: "memory");
        __syncthreads();
        if (ch + 2 < NCH) STAGE((ch + 2) % 3, (size_t)(ch + 2) * KC);

        const int slot = ch % 3;
        const uint32_t pA = sbase + slot * SBYT;
        const uint32_t pB = sbase + (3 + slot) * SBYT;

#pragma unroll
        for (int ks = 0; ks < 2; ks++) {
            const uint32_t k0 = (uint32_t)ks * 32 + (uint32_t)q * 8;
            uint32_t a[4][4], b[4][2];
#pragma unroll
            for (int mt = 0; mt < 4; mt++) {
                const uint32_t ra = pA + (uint32_t)((wm + mt * 16 + g) * RSB) + k0;
                LDSD(a[mt][0], a[mt][2], ra);
                LDSD(a[mt][1], a[mt][3], ra + 8 * RSB);
            }
#pragma unroll
            for (int nt = 0; nt < 4; nt++) {
                const uint32_t rb = pB + (uint32_t)((wn + nt * 8 + g) * RSB) + k0;
                LDSD(b[nt][0], b[nt][1], rb);
            }
#pragma unroll
            for (int mt = 0; mt < 4; mt++)
#pragma unroll
                for (int nt = 0; nt < 4; nt++)
                    MMA_F16(acc[mt][nt], a[mt][0], a[mt][1], a[mt][2], a[mt][3],
                            b[nt][0], b[nt][1]);
        }
    }

    // epilogue: fp16 half2 stores to g_outTh[w][b][i]
#pragma unroll
    for (int mt = 0; mt < 4; mt++) {
        const int row = b0 + wm + mt * 16 + g;
#pragma unroll
        for (int nt = 0; nt < 4; nt++) {
            const int col = i0 + wn + nt * 8 + 2 * q;
            __half2 v0 = __floats2half2_rn(acc[mt][nt][0], acc[mt][nt][1]);
            __half2 v1 = __floats2half2_rn(acc[mt][nt][2], acc[mt][nt][3]);
            *(__half2*)&g_outTh[((size_t)w * NB + row)     * NI + col] = v0;
            *(__half2*)&g_outTh[((size_t)w * NB + row + 8) * NI + col] = v1;
        }
    }
}

// ---------------------------------------------------------------------------
// Kernel 3: transpose outTh[w][b][i] (fp16) -> out[b][i][w] (f32)
// ---------------------------------------------------------------------------
__global__ void __launch_bounds__(256) tout_kernel(float* __restrict__ out) {
    __shared__ float s[32][65];
    const int b  = blockIdx.y;
    const int i0 = blockIdx.x * 32;
    const int t  = threadIdx.x;

    {   // load 64 w-rows x 32 i (fp16, 16B per thread)
        int w = t >> 2, ig = (t & 3) * 8;
        uint4 raw = *(const uint4*)&g_outTh[((size_t)w * NB + b) * NI + i0 + ig];
        const __half2* hp = (const __half2*)&raw;
#pragma unroll
        for (int u = 0; u < 4; u++) {
            float2 f = __half22float2(hp[u]);
            s[ig + 2 * u][w]     = f.x;
            s[ig + 2 * u + 1][w] = f.y;
        }
    }
    __syncthreads();
    {   // write 32 i-rows x 64 w (256B per row)
        int r = t >> 3, wq = (t & 7) * 8;
        float* dst = out + ((size_t)b * NI + i0 + r) * NW + wq;
        float4 o0, o1;
        o0.x = s[r][wq + 0]; o0.y = s[r][wq + 1]; o0.z = s[r][wq + 2]; o0.w = s[r][wq + 3];
        o1.x = s[r][wq + 4]; o1.y = s[r][wq + 5]; o1.z = s[r][wq + 6]; o1.w = s[r][wq + 7];
        ((float4*)dst)[0] = o0; ((float4*)dst)[1] = o1;
    }
}

// ---------------------------------------------------------------------------
extern "C" void kernel_launch(void* const* d_in, const int* in_sizes, int n_in,
                              void* d_out, int out_size) {
    const float* input    = (const float*)d_in[0];  // [256,512,64]
    const float* phase    = (const float*)d_in[1];  // [512,512]
    const float* coupling = (const float*)d_in[2];  // [512,512]
    float* out            = (float*)d_out;          // [256,512,64]

    cudaFuncSetAttribute(gemm_kernel, cudaFuncAttributeMaxDynamicSharedMemorySize, SMEM_REQ);

    prep_kernel<<<256 + 4096, 256>>>(input, phase, coupling);
    gemm_kernel<<<dim3(NW, NB / TM, NI / TN), 256, SMEM_REQ>>>();
    tout_kernel<<<dim3(NI / 32, NB), 256>>>(out);
}